// round 7
// baseline (speedup 1.0000x reference)
#include <cuda_runtime.h>

// CVXPolicy_Integrator, persistent tf32-mma, round 7:
// k1: NT=512, 64-col chunks (5 bars/tile), balanced {4,3,3,3} n-split.
// k2: round-5 mainloop + packed f32x2 epilogue.

#define Bq    131072
#define Dq    256
#define Hq    100
#define GRID  148
#define NT    512
#define NTILES (Bq / 128)   // 1024

#define NP1   104      // padded H
#define SW1   264      // w1t row stride (==8 mod 32)
#define XSW   72       // xs row stride (==8 mod 32): 64 data + 8 pad
#define XBUF  (128 * XSW)
#define SW2   104      // w2t/hs row stride (==8 mod 32, dense)

// hidden activations, tf32 bits, k-PERMUTED columns, [B][104]
__device__ unsigned g_H[(size_t)Bq * NP1];

// ---------------- helpers ----------------
__device__ __forceinline__ unsigned cvt_tf32(float f) {
    unsigned u;
    asm("cvt.rna.tf32.f32 %0, %1;" : "=r"(u) : "f"(f));
    return u;
}
__device__ __forceinline__ void mma_tf32(float* c,
                                         unsigned a0, unsigned a1, unsigned a2, unsigned a3,
                                         unsigned b0, unsigned b1) {
    asm volatile(
        "mma.sync.aligned.m16n8k8.row.col.f32.tf32.tf32.f32 "
        "{%0,%1,%2,%3}, {%4,%5,%6,%7}, {%8,%9}, {%0,%1,%2,%3};"
        : "+f"(c[0]), "+f"(c[1]), "+f"(c[2]), "+f"(c[3])
        : "r"(a0), "r"(a1), "r"(a2), "r"(a3), "r"(b0), "r"(b1));
}
__device__ __forceinline__ void cp_async16(void* sdst, const void* gsrc) {
    unsigned s = (unsigned)__cvta_generic_to_shared(sdst);
    asm volatile("cp.async.cg.shared.global [%0], [%1], 16;" :: "r"(s), "l"(gsrc));
}
#define CP_COMMIT() asm volatile("cp.async.commit_group;")
#define CP_WAIT(n)  asm volatile("cp.async.wait_group %0;" :: "n"(n))

// within each 8-block: position(k) = (k&3)<<1 | ((k>>2)&1); pairs {k,k+4} adjacent
__device__ __forceinline__ int permk(int k) {
    return (k & ~7) | ((k & 3) << 1) | ((k >> 2) & 1);
}

// packed f32x2 (per-lane IEEE identical to scalar)
union F2U { float2 f; unsigned long long u; };
__device__ __forceinline__ float2 add2(float2 a, float2 b) {
    F2U A, B, C; A.f = a; B.f = b;
    asm("add.rn.f32x2 %0, %1, %2;" : "=l"(C.u) : "l"(A.u), "l"(B.u));
    return C.f;
}
__device__ __forceinline__ float2 fma2(float2 a, float2 b, float2 c) {
    F2U A, B, C, D; A.f = a; B.f = b; C.f = c;
    asm("fma.rn.f32x2 %0, %1, %2, %3;" : "=l"(D.u) : "l"(A.u), "l"(B.u), "l"(C.u));
    return D.f;
}
__device__ __forceinline__ float2 mul2(float2 a, float2 b) {
    F2U A, B, C; A.f = a; B.f = b;
    asm("mul.rn.f32x2 %0, %1, %2;" : "=l"(C.u) : "l"(A.u), "l"(B.u));
    return C.f;
}

__device__ __forceinline__ float tanh_fast(float x) {
    float ax = fabsf(x);
    float e  = __expf(-2.0f * ax);
    float y  = 1.0f + e;
    float r  = __uint_as_float(0x7EF311C3u - __float_as_uint(y));
    r = r * (2.0f - y * r);
    r = r * (2.0f - y * r);
    r = r * (2.0f - y * r);
    float th = fmaf(-2.0f * e, r, 1.0f);
    return copysignf(th, x);
}

// ---------------- kernel 1: h = tanh([z,t]@W1+b1) ----------------
// smem: w1t[104][264] + xs[3][128][72] + b1s[104]  (~221 KB)
#define SMEM1 ((NP1 * SW1 + 3 * XBUF + NP1) * 4)

__global__ void __launch_bounds__(NT, 1)
k1_hidden(const float* __restrict__ z, const float* __restrict__ t,
          const float* __restrict__ W1, const float* __restrict__ b1)
{
    extern __shared__ unsigned sm[];
    unsigned* w1t = sm;
    unsigned* xs  = sm + NP1 * SW1;
    float*    b1s = (float*)(sm + NP1 * SW1 + 3 * XBUF);

    const int tid = threadIdx.x;

    // one-time: W1 transpose + k-rotate (t at k=256) + k-perm
    for (int idx = tid; idx < 257 * Hq; idx += NT) {
        int k = idx / Hq, n = idx - k * Hq;
        int kk = (k == 0) ? 256 : (k - 1);
        w1t[n * SW1 + permk(kk)] = cvt_tf32(W1[idx]);
    }
    for (int idx = tid; idx < NP1 * 7; idx += NT) {
        int n = idx / 7, j = idx - n * 7;
        w1t[n * SW1 + 257 + j] = 0u;
    }
    for (int idx = tid; idx < 4 * SW1; idx += NT) {
        int n = 100 + idx / SW1, j = idx % SW1;
        w1t[n * SW1 + j] = 0u;
    }
    if (tid < NP1) b1s[tid] = (tid < Hq) ? b1[tid] : 0.0f;

    const int warp = tid >> 5, lane = tid & 31;
    const int gid = lane >> 2, tig = lane & 3;
    const int m0  = (warp & 3) * 32;                   // 4 m-groups of 32 rows
    const int ng  = warp >> 2;                         // 4 n-groups over 13 tiles
    const int tb  = ng ? (1 + 3 * ng) : 0;             // {0,4,7,10}
    const int ntc = ng ? 3 : 4;                        // {4,3,3,3}
    const int mr  = m0 + gid;

    // staging: thread covers row sr, 16-col slice sb of each 64-col chunk
    const int sr = tid >> 2, sb = tid & 3;

    // chunks: 4 z-chunks of 64 cols + 1 t-chunk
    int pt = blockIdx.x, pc = 0;
    float4 r0v = make_float4(0.f, 0.f, 0.f, 0.f), r1v = r0v, r2v = r0v, r3v = r0v;

    #define K1_LDG() do {                                                        \
        if (pt < NTILES) {                                                       \
            if (pc < 4) {                                                        \
                const float4* src = (const float4*)z                             \
                    + ((size_t)(pt * 128 + sr)) * 64 + pc * 16 + sb * 4;         \
                r0v = src[0]; r1v = src[1]; r2v = src[2]; r3v = src[3];          \
            } else {                                                             \
                r0v = make_float4(0.f, 0.f, 0.f, 0.f);                           \
                r1v = r0v; r2v = r0v; r3v = r0v;                                 \
                if (sb == 0) r0v.x = t[pt * 128 + sr];                           \
            }                                                                    \
        }                                                                        \
        pc++; if (pc == 5) { pc = 0; pt += GRID; }                               \
    } while (0)

    // permuted store: per 8-col block, positions {c0,c4,c1,c5,c2,c6,c3,c7}
    #define K1_STS(bs) do {                                                      \
        unsigned* d = xs + (bs) * XBUF + sr * XSW + sb * 16;                     \
        uint4 u;                                                                 \
        u.x = cvt_tf32(r0v.x); u.y = cvt_tf32(r1v.x);                            \
        u.z = cvt_tf32(r0v.y); u.w = cvt_tf32(r1v.y);                            \
        *(uint4*)(d) = u;                                                        \
        u.x = cvt_tf32(r0v.z); u.y = cvt_tf32(r1v.z);                            \
        u.z = cvt_tf32(r0v.w); u.w = cvt_tf32(r1v.w);                            \
        *(uint4*)(d + 4) = u;                                                    \
        u.x = cvt_tf32(r2v.x); u.y = cvt_tf32(r3v.x);                            \
        u.z = cvt_tf32(r2v.y); u.w = cvt_tf32(r3v.y);                            \
        *(uint4*)(d + 8) = u;                                                    \
        u.x = cvt_tf32(r2v.z); u.y = cvt_tf32(r3v.z);                            \
        u.z = cvt_tf32(r2v.w); u.w = cvt_tf32(r3v.w);                            \
        *(uint4*)(d + 12) = u;                                                   \
    } while (0)

    K1_LDG();          // chunk 0 -> regs
    K1_STS(0);         // chunk 0 -> buf0
    K1_LDG();          // chunk 1 -> regs
    __syncthreads();

    float acc[4][2][4];
    #pragma unroll
    for (int nt = 0; nt < 4; nt++)
        #pragma unroll
        for (int mf = 0; mf < 2; mf++)
            #pragma unroll
            for (int i = 0; i < 4; i++) acc[nt][mf][i] = 0.0f;

    int bcur = 0;
    for (int tile = blockIdx.x; tile < NTILES; tile += GRID) {
        for (int cc = 0; cc < 5; cc++) {
            int bnext = bcur + 1; if (bnext == 3) bnext = 0;
            K1_STS(bnext);      // stage chunk g+1 (from regs)
            K1_LDG();           // fetch chunk g+2 into regs
            __syncthreads();

            const unsigned* xa = xs + bcur * XBUF + mr * XSW + 2 * tig;
            const unsigned* wb = w1t + (tb * 8 + gid) * SW1 + cc * 64 + 2 * tig;
            const int kst = (cc == 4) ? 1 : 8;
            #pragma unroll
            for (int ks = 0; ks < 8; ks++) {
                if (ks < kst) {
                    const int k0 = ks * 8;
                    uint2 A0 = *(const uint2*)(xa + k0);
                    uint2 A1 = *(const uint2*)(xa + 8 * XSW + k0);
                    uint2 A2 = *(const uint2*)(xa + 16 * XSW + k0);
                    uint2 A3 = *(const uint2*)(xa + 24 * XSW + k0);
                    #pragma unroll
                    for (int nt = 0; nt < 4; nt++) {
                        if (nt < ntc) {
                            uint2 bb = *(const uint2*)(wb + nt * 8 * SW1 + k0);
                            mma_tf32(acc[nt][0], A0.x, A1.x, A0.y, A1.y, bb.x, bb.y);
                            mma_tf32(acc[nt][1], A2.x, A3.x, A2.y, A3.y, bb.x, bb.y);
                        }
                    }
                }
            }
            bcur = bnext;
        }

        // epilogue: bias + tanh + store k-PERMUTED to g_H
        size_t rowb = (size_t)tile * 128 + mr;
        #pragma unroll
        for (int nt = 0; nt < 4; nt++) {
            if (nt < ntc) {
                int col = (tb + nt) * 8 + 2 * tig;
                float bb0 = b1s[col], bb1 = b1s[col + 1];
                int c0 = permk(col), c1 = permk(col + 1);
                #pragma unroll
                for (int mf = 0; mf < 2; mf++) {
                    size_t r0 = rowb + mf * 16;
                    g_H[r0 * NP1 + c0]       = cvt_tf32(tanh_fast(acc[nt][mf][0] + bb0));
                    g_H[r0 * NP1 + c1]       = cvt_tf32(tanh_fast(acc[nt][mf][1] + bb1));
                    g_H[(r0 + 8) * NP1 + c0] = cvt_tf32(tanh_fast(acc[nt][mf][2] + bb0));
                    g_H[(r0 + 8) * NP1 + c1] = cvt_tf32(tanh_fast(acc[nt][mf][3] + bb1));
                    acc[nt][mf][0] = acc[nt][mf][1] = acc[nt][mf][2] = acc[nt][mf][3] = 0.0f;
                }
            }
        }
    }
}

// ---------------- kernel 2 ----------------
// smem: w2t[256][104] + hs[2][128][104] + b2s[256] + r2p[4][128] + scs[128]
#define HBUF  (128 * SW2)
#define SMEM2 ((Dq * SW2 + 2 * HBUF + Dq + 512 + 128) * 4)

__device__ __forceinline__ void k2_prefetch(unsigned* hbuf, int tile, int tid) {
    const uint4* src = (const uint4*)(g_H + (size_t)tile * 128 * NP1);
    #pragma unroll
    for (int j = 0; j < 7; j++) {
        int idx = j * NT + tid;
        if (idx < 128 * 26) cp_async16(hbuf + idx * 4, src + idx);
    }
}

__global__ void __launch_bounds__(NT, 1)
k2_policy(const float* __restrict__ W2, const float* __restrict__ b2,
          float* __restrict__ out)
{
    extern __shared__ unsigned sm2[];
    unsigned* w2t = sm2;
    unsigned* hs  = sm2 + Dq * SW2;
    float*    b2s = (float*)(sm2 + Dq * SW2 + 2 * HBUF);
    float*    r2p = b2s + Dq;      // [4][128]
    float*    scs = r2p + 512;     // [128]

    const int tid = threadIdx.x;

    for (int idx = tid; idx < Hq * Dq; idx += NT) {
        int k = idx >> 8, n = idx & 255;
        w2t[n * SW2 + permk(k)] = cvt_tf32(W2[idx]);
    }
    for (int idx = tid; idx < Dq * 4; idx += NT) {
        int n = idx >> 2, j = idx & 3;
        w2t[n * SW2 + 97 + 2 * j] = 0u;   // pads for k=100..103
    }
    if (tid < Dq) b2s[tid] = b2[tid];

    k2_prefetch(hs, blockIdx.x, tid);
    CP_COMMIT();
    __syncthreads();

    const int warp = tid >> 5, lane = tid & 31;
    const int gid = lane >> 2, tig = lane & 3;
    const int m0 = (warp & 3) * 32;
    const int ng = warp >> 2;
    const int n0 = ng * 64;
    const int mr = m0 + gid;

    int bi = 0;
    for (int tile = blockIdx.x; tile < NTILES; tile += GRID) {
        CP_WAIT(0);
        __syncthreads();
        if (tile + GRID < NTILES) k2_prefetch(hs + (bi ^ 1) * HBUF, tile + GRID, tid);
        CP_COMMIT();

        float acc[8][2][4];
        #pragma unroll
        for (int nt = 0; nt < 8; nt++)
            #pragma unroll
            for (int mf = 0; mf < 2; mf++)
                #pragma unroll
                for (int i = 0; i < 4; i++) acc[nt][mf][i] = 0.0f;

        const unsigned* ha = hs + bi * HBUF + mr * SW2 + 2 * tig;
        const unsigned* wb = w2t + (n0 + gid) * SW2 + 2 * tig;

        #pragma unroll
        for (int ks = 0; ks < 13; ks++) {
            const int k0 = ks * 8;
            uint2 A0 = *(const uint2*)(ha + k0);
            uint2 A1 = *(const uint2*)(ha + 8 * SW2 + k0);
            uint2 A2 = *(const uint2*)(ha + 16 * SW2 + k0);
            uint2 A3 = *(const uint2*)(ha + 24 * SW2 + k0);
            #pragma unroll
            for (int nt = 0; nt < 8; nt++) {
                uint2 bb = *(const uint2*)(wb + nt * 8 * SW2 + k0);
                mma_tf32(acc[nt][0], A0.x, A1.x, A0.y, A1.y, bb.x, bb.y);
                mma_tf32(acc[nt][1], A2.x, A3.x, A2.y, A3.y, bb.x, bb.y);
            }
        }

        // packed epilogue: bias + per-row ||p||^2 partials (f32x2)
        float2 S0 = make_float2(0.f, 0.f), S1 = S0, S2 = S0, S3 = S0;
        #pragma unroll
        for (int nt = 0; nt < 8; nt++) {
            int col = n0 + nt * 8 + 2 * tig;
            float2 b01 = *(const float2*)&b2s[col];
            float2 v0 = add2(make_float2(acc[nt][0][0], acc[nt][0][1]), b01);
            float2 v1 = add2(make_float2(acc[nt][0][2], acc[nt][0][3]), b01);
            float2 v2 = add2(make_float2(acc[nt][1][0], acc[nt][1][1]), b01);
            float2 v3 = add2(make_float2(acc[nt][1][2], acc[nt][1][3]), b01);
            S0 = fma2(v0, v0, S0);
            S1 = fma2(v1, v1, S1);
            S2 = fma2(v2, v2, S2);
            S3 = fma2(v3, v3, S3);
            acc[nt][0][0] = v0.x; acc[nt][0][1] = v0.y;
            acc[nt][0][2] = v1.x; acc[nt][0][3] = v1.y;
            acc[nt][1][0] = v2.x; acc[nt][1][1] = v2.y;
            acc[nt][1][2] = v3.x; acc[nt][1][3] = v3.y;
        }
        float s0 = S0.x + S0.y, s1 = S1.x + S1.y;
        float s2 = S2.x + S2.y, s3 = S3.x + S3.y;
        s0 += __shfl_xor_sync(0xffffffffu, s0, 1); s0 += __shfl_xor_sync(0xffffffffu, s0, 2);
        s1 += __shfl_xor_sync(0xffffffffu, s1, 1); s1 += __shfl_xor_sync(0xffffffffu, s1, 2);
        s2 += __shfl_xor_sync(0xffffffffu, s2, 1); s2 += __shfl_xor_sync(0xffffffffu, s2, 2);
        s3 += __shfl_xor_sync(0xffffffffu, s3, 1); s3 += __shfl_xor_sync(0xffffffffu, s3, 2);
        if (tig == 0) {
            r2p[ng * 128 + mr]      = s0;
            r2p[ng * 128 + mr + 8]  = s1;
            r2p[ng * 128 + mr + 16] = s2;
            r2p[ng * 128 + mr + 24] = s3;
        }
        __syncthreads();

        // Lambert-W Newton (warps 0-3; 1 per SMSP), reference recurrence
        if (tid < 128) {
            float r2 = r2p[tid] + r2p[128 + tid] + r2p[256 + tid] + r2p[384 + tid];
            float w = log1pf(r2);
            #pragma unroll
            for (int it = 0; it < 10; it++) {
                float ew  = __expf(w);
                float num = fmaf(w, ew, -r2);
                float den = fmaf(w, ew, ew);
                w = w - __fdividef(num, den);
            }
            w = fmaxf(w, 0.0f);
            float tn = sqrtf(w);
            float rr = sqrtf(r2);
            float scale = (rr > 1e-12f) ? __fdividef(tn, fmaxf(rr, 1e-12f)) : 1.0f;
            scs[tid] = -scale;
        }
        __syncthreads();

        const float2 sc0 = make_float2(scs[mr], scs[mr]);
        const float2 sc1 = make_float2(scs[mr + 8], scs[mr + 8]);
        const float2 sc2 = make_float2(scs[mr + 16], scs[mr + 16]);
        const float2 sc3 = make_float2(scs[mr + 24], scs[mr + 24]);
        const size_t rb = ((size_t)tile * 128 + mr) * Dq;
        #pragma unroll
        for (int nt = 0; nt < 8; nt++) {
            int col = n0 + nt * 8 + 2 * tig;
            *(float2*)&out[rb + col]           = mul2(sc0, make_float2(acc[nt][0][0], acc[nt][0][1]));
            *(float2*)&out[rb + 8  * Dq + col] = mul2(sc1, make_float2(acc[nt][0][2], acc[nt][0][3]));
            *(float2*)&out[rb + 16 * Dq + col] = mul2(sc2, make_float2(acc[nt][1][0], acc[nt][1][1]));
            *(float2*)&out[rb + 24 * Dq + col] = mul2(sc3, make_float2(acc[nt][1][2], acc[nt][1][3]));
        }
        bi ^= 1;
    }
}

// ---------------- launch ----------------
extern "C" void kernel_launch(void* const* d_in, const int* in_sizes, int n_in,
                              void* d_out, int out_size)
{
    const float* z  = (const float*)d_in[0];
    const float* t  = (const float*)d_in[1];
    const float* W1 = (const float*)d_in[2];
    const float* b1 = (const float*)d_in[3];
    const float* W2 = (const float*)d_in[4];
    const float* b2 = (const float*)d_in[5];
    float* out = (float*)d_out;

    cudaFuncSetAttribute(k1_hidden, cudaFuncAttributeMaxDynamicSharedMemorySize, SMEM1);
    cudaFuncSetAttribute(k2_policy, cudaFuncAttributeMaxDynamicSharedMemorySize, SMEM2);

    k1_hidden<<<GRID, NT, SMEM1>>>(z, t, W1, b1);
    k2_policy<<<GRID, NT, SMEM2>>>(W2, b2, out);
}

// round 8
// speedup vs baseline: 1.3981x; 1.3981x over previous
#include <cuda_runtime.h>

// CVXPolicy_Integrator, persistent fp16-mma (m16n8k16, fp32 accum), round 8.
// k1: h = tanh([z,t]@W1+b1) -> g_H fp16 (k-permuted half2), round-5 stream structure.
// k2: p = h@W2+b2; r2; LambertW; ustar. Dense 56-u32 rows (stride%32==24: conflict-free).

#define Bq    131072
#define Dq    256
#define Hq    100
#define HP    112          // padded hidden (7 k16-steps), 56 u32 per row
#define HPU   56
#define GRID  148
#define NT    512
#define NTILES (Bq / 128)  // 1024

#define W1SW  136          // w1t row stride in u32 (136%32==8)
#define XSW   24           // xs row stride in u32  (24%32==24)
#define XBUF  (128 * XSW)
#define KP1U  136          // GEMM1 K in u32 (272 halves: 256 z + t + pad)

// hidden activations: packed half2 (u32), k-permuted, [B][56]
__device__ unsigned g_H[(size_t)Bq * HPU];

// ---------------- helpers ----------------
__device__ __forceinline__ unsigned pack_h2(float lo, float hi) {
    unsigned u;
    asm("cvt.rn.f16x2.f32 %0, %1, %2;" : "=r"(u) : "f"(hi), "f"(lo));
    return u;
}
__device__ __forceinline__ void mma_f16(float* c,
                                        unsigned a0, unsigned a1, unsigned a2, unsigned a3,
                                        unsigned b0, unsigned b1) {
    asm volatile(
        "mma.sync.aligned.m16n8k16.row.col.f32.f16.f16.f32 "
        "{%0,%1,%2,%3}, {%4,%5,%6,%7}, {%8,%9}, {%0,%1,%2,%3};"
        : "+f"(c[0]), "+f"(c[1]), "+f"(c[2]), "+f"(c[3])
        : "r"(a0), "r"(a1), "r"(a2), "r"(a3), "r"(b0), "r"(b1));
}
__device__ __forceinline__ void cp_async16(void* sdst, const void* gsrc) {
    unsigned s = (unsigned)__cvta_generic_to_shared(sdst);
    asm volatile("cp.async.cg.shared.global [%0], [%1], 16;" :: "r"(s), "l"(gsrc));
}
#define CP_COMMIT() asm volatile("cp.async.commit_group;")
#define CP_WAIT(n)  asm volatile("cp.async.wait_group %0;" :: "n"(n))

// u32-granularity perm within 8-blocks: pairs {u,u+4} -> {2v,2v+1}
__device__ __forceinline__ int permu(int u) {
    return (u & ~7) | ((u & 3) << 1) | ((u >> 2) & 1);
}

union F2U { float2 f; unsigned long long u; };
__device__ __forceinline__ float2 add2(float2 a, float2 b) {
    F2U A, B, C; A.f = a; B.f = b;
    asm("add.rn.f32x2 %0, %1, %2;" : "=l"(C.u) : "l"(A.u), "l"(B.u));
    return C.f;
}
__device__ __forceinline__ float2 fma2(float2 a, float2 b, float2 c) {
    F2U A, B, C, D; A.f = a; B.f = b; C.f = c;
    asm("fma.rn.f32x2 %0, %1, %2, %3;" : "=l"(D.u) : "l"(A.u), "l"(B.u), "l"(C.u));
    return D.f;
}
__device__ __forceinline__ float2 mul2(float2 a, float2 b) {
    F2U A, B, C; A.f = a; B.f = b;
    asm("mul.rn.f32x2 %0, %1, %2;" : "=l"(C.u) : "l"(A.u), "l"(B.u));
    return C.f;
}

__device__ __forceinline__ float tanh_fast(float x) {
    float ax = fabsf(x);
    float e  = __expf(-2.0f * ax);
    float y  = 1.0f + e;
    float r  = __uint_as_float(0x7EF311C3u - __float_as_uint(y));
    r = r * (2.0f - y * r);
    r = r * (2.0f - y * r);
    r = r * (2.0f - y * r);
    float th = fmaf(-2.0f * e, r, 1.0f);
    return copysignf(th, x);
}

// ---------------- kernel 1: h = tanh([z,t]@W1+b1) ----------------
// smem: w1t[112][136]u32 + xs[3][128][24]u32 + b1s[112]  (~96 KB)
#define SMEM1 ((HP * W1SW + 3 * XBUF + HP) * 4)

__global__ void __launch_bounds__(NT, 1)
k1_hidden(const float* __restrict__ z, const float* __restrict__ t,
          const float* __restrict__ W1, const float* __restrict__ b1)
{
    extern __shared__ unsigned sm[];
    unsigned* w1t = sm;
    unsigned* xs  = sm + HP * W1SW;
    float*    b1s = (float*)(sm + HP * W1SW + 3 * XBUF);

    const int tid = threadIdx.x;

    // one-time: W1 -> w1t[n][perm(u)] packed half2. X col kk<256 pairs W1 row kk+1;
    // kk=256 -> W1 row 0; kk>256 -> 0; n>=100 -> 0.
    for (int idx = tid; idx < HP * KP1U; idx += NT) {
        int u = idx / HP, n = idx - u * HP;
        float f0 = 0.0f, f1 = 0.0f;
        if (n < Hq) {
            int k0 = 2 * u, k1 = 2 * u + 1;
            f0 = (k0 == 256) ? W1[n] : ((k0 < 256) ? W1[(k0 + 1) * Hq + n] : 0.0f);
            f1 = (k1 == 256) ? W1[n] : ((k1 < 256) ? W1[(k1 + 1) * Hq + n] : 0.0f);
        }
        w1t[n * W1SW + permu(u)] = pack_h2(f0, f1);
    }
    if (tid < HP) b1s[tid] = (tid < Hq) ? b1[tid] : 0.0f;

    const int warp = tid >> 5, lane = tid & 31;
    const int gid = lane >> 2, tig = lane & 3;
    const int m0  = (warp & 3) * 32;                 // 4 m-groups of 32 rows
    const int ng  = warp >> 2;                       // 4 n-groups over 14 tiles
    const int tb  = (ng < 2) ? 4 * ng : (8 + 3 * (ng - 2));  // {0,4,8,11}
    const int ntc = (ng < 2) ? 4 : 3;                        // {4,4,3,3}
    const int mr  = m0 + gid;

    // staging: thread = (row sr, quarter sb) of each 32-col chunk
    const int sr = tid >> 2, sb = tid & 3;
    const int q0 = (sb >> 1) * 4 + (sb & 1);   // float4 indices {0,1,4,5}; q1=q0+2

    // chunks: 8 z-chunks of 32 cols + 1 t-chunk; ring of 3
    int pt = blockIdx.x, pc = 0;
    float4 rA = make_float4(0.f, 0.f, 0.f, 0.f), rB = rA;

    #define K1_LDG() do {                                                        \
        if (pt < NTILES) {                                                       \
            if (pc < 8) {                                                        \
                const float4* src = (const float4*)z                             \
                    + ((size_t)(pt * 128 + sr)) * 64 + pc * 8;                   \
                rA = src[q0]; rB = src[q0 + 2];                                  \
            } else {                                                             \
                rA = make_float4(0.f, 0.f, 0.f, 0.f); rB = rA;                   \
                if (sb == 0) rA.x = t[pt * 128 + sr];                            \
            }                                                                    \
        }                                                                        \
        pc++; if (pc == 9) { pc = 0; pt += GRID; }                               \
    } while (0)

    // permuted pack: uint4 at positions 4sb..4sb+3 = {h2(A.xy), h2(B.xy), h2(A.zw), h2(B.zw)}
    #define K1_STS(bs) do {                                                      \
        unsigned* d = xs + (bs) * XBUF + sr * XSW + sb * 4;                      \
        uint4 u;                                                                 \
        u.x = pack_h2(rA.x, rA.y); u.y = pack_h2(rB.x, rB.y);                    \
        u.z = pack_h2(rA.z, rA.w); u.w = pack_h2(rB.z, rB.w);                    \
        *(uint4*)d = u;                                                          \
    } while (0)

    K1_LDG();
    K1_STS(0);
    K1_LDG();
    __syncthreads();

    float acc[4][2][4];
    #pragma unroll
    for (int nt = 0; nt < 4; nt++)
        #pragma unroll
        for (int mf = 0; mf < 2; mf++)
            #pragma unroll
            for (int i = 0; i < 4; i++) acc[nt][mf][i] = 0.0f;

    int bcur = 0;
    for (int tile = blockIdx.x; tile < NTILES; tile += GRID) {
        for (int cc = 0; cc < 9; cc++) {
            int bnext = bcur + 1; if (bnext == 3) bnext = 0;
            K1_STS(bnext);
            K1_LDG();
            __syncthreads();

            const unsigned* xa = xs + bcur * XBUF + mr * XSW + 2 * tig;
            const unsigned* wb = w1t + (tb * 8 + gid) * W1SW + cc * 16 + 2 * tig;
            const int kst = (cc == 8) ? 1 : 2;
            #pragma unroll
            for (int ks = 0; ks < 2; ks++) {
                if (ks < kst) {
                    const int u0 = ks * 8;
                    uint2 A0 = *(const uint2*)(xa + u0);            // row mr   (a0,a2)
                    uint2 A1 = *(const uint2*)(xa + 8 * XSW + u0);  // row mr+8 (a1,a3)
                    uint2 A2 = *(const uint2*)(xa + 16 * XSW + u0);
                    uint2 A3 = *(const uint2*)(xa + 24 * XSW + u0);
                    #pragma unroll
                    for (int nt = 0; nt < 4; nt++) {
                        if (nt < ntc) {
                            uint2 bb = *(const uint2*)(wb + nt * 8 * W1SW + u0);
                            mma_f16(acc[nt][0], A0.x, A1.x, A0.y, A1.y, bb.x, bb.y);
                            mma_f16(acc[nt][1], A2.x, A3.x, A2.y, A3.y, bb.x, bb.y);
                        }
                    }
                }
            }
            bcur = bnext;
        }

        // epilogue: bias + tanh + packed-half2 store, k-permuted (pads n>=100 are 0 naturally)
        size_t rowb = (size_t)tile * 128 + mr;
        #pragma unroll
        for (int nt = 0; nt < 4; nt++) {
            if (nt < ntc) {
                int u   = (tb + nt) * 4 + tig;     // u32 index: halves {2u,2u+1}
                int col = 2 * u;
                int pos = permu(u);
                float bb0 = b1s[col], bb1 = b1s[col + 1];
                #pragma unroll
                for (int mf = 0; mf < 2; mf++) {
                    size_t r0 = rowb + mf * 16;
                    g_H[r0 * HPU + pos] =
                        pack_h2(tanh_fast(acc[nt][mf][0] + bb0), tanh_fast(acc[nt][mf][1] + bb1));
                    g_H[(r0 + 8) * HPU + pos] =
                        pack_h2(tanh_fast(acc[nt][mf][2] + bb0), tanh_fast(acc[nt][mf][3] + bb1));
                    acc[nt][mf][0] = acc[nt][mf][1] = acc[nt][mf][2] = acc[nt][mf][3] = 0.0f;
                }
            }
        }
    }
}

// ---------------- kernel 2 ----------------
// smem: w2t[256][56]u32 + hs[2][128][56]u32 + b2s[256] + r2p[4][128] + scs[128] (~118 KB)
#define HBUF  (128 * HPU)
#define SMEM2 ((Dq * HPU + 2 * HBUF + Dq + 512 + 128) * 4)

__device__ __forceinline__ void k2_prefetch(unsigned* hbuf, int tile, int tid) {
    const uint4* src = (const uint4*)(g_H + (size_t)tile * 128 * HPU);
    #pragma unroll
    for (int j = 0; j < 4; j++) {
        int idx = j * NT + tid;
        if (idx < 128 * 14) cp_async16(hbuf + idx * 4, src + idx);   // dense rows
    }
}

__global__ void __launch_bounds__(NT, 1)
k2_policy(const float* __restrict__ W2, const float* __restrict__ b2,
          float* __restrict__ out)
{
    extern __shared__ unsigned sm2[];
    unsigned* w2t = sm2;
    unsigned* hs  = sm2 + Dq * HPU;
    float*    b2s = (float*)(sm2 + Dq * HPU + 2 * HBUF);
    float*    r2p = b2s + Dq;      // [4][128]
    float*    scs = r2p + 512;     // [128]

    const int tid = threadIdx.x;

    // one-time: W2 -> w2t[n][perm(u)] packed half2 (k pads 100..111 zero)
    for (int idx = tid; idx < HPU * Dq; idx += NT) {
        int u = idx >> 8, n = idx & 255;
        int k0 = 2 * u, k1 = 2 * u + 1;
        float f0 = (k0 < Hq) ? W2[k0 * Dq + n] : 0.0f;
        float f1 = (k1 < Hq) ? W2[k1 * Dq + n] : 0.0f;
        w2t[n * HPU + permu(u)] = pack_h2(f0, f1);
    }
    if (tid < Dq) b2s[tid] = b2[tid];

    k2_prefetch(hs, blockIdx.x, tid);
    CP_COMMIT();
    __syncthreads();

    const int warp = tid >> 5, lane = tid & 31;
    const int gid = lane >> 2, tig = lane & 3;
    const int m0 = (warp & 3) * 32;
    const int ng = warp >> 2;
    const int n0 = ng * 64;
    const int mr = m0 + gid;

    int bi = 0;
    for (int tile = blockIdx.x; tile < NTILES; tile += GRID) {
        CP_WAIT(0);
        __syncthreads();
        if (tile + GRID < NTILES) k2_prefetch(hs + (bi ^ 1) * HBUF, tile + GRID, tid);
        CP_COMMIT();

        float acc[8][2][4];
        #pragma unroll
        for (int nt = 0; nt < 8; nt++)
            #pragma unroll
            for (int mf = 0; mf < 2; mf++)
                #pragma unroll
                for (int i = 0; i < 4; i++) acc[nt][mf][i] = 0.0f;

        const unsigned* ha = hs + bi * HBUF + mr * HPU + 2 * tig;
        const unsigned* wb = w2t + (n0 + gid) * HPU + 2 * tig;

        #pragma unroll
        for (int ks = 0; ks < 7; ks++) {
            const int u0 = ks * 8;
            uint2 A0 = *(const uint2*)(ha + u0);
            uint2 A1 = *(const uint2*)(ha + 8 * HPU + u0);
            uint2 A2 = *(const uint2*)(ha + 16 * HPU + u0);
            uint2 A3 = *(const uint2*)(ha + 24 * HPU + u0);
            #pragma unroll
            for (int nt = 0; nt < 8; nt++) {
                uint2 bb = *(const uint2*)(wb + nt * 8 * HPU + u0);
                mma_f16(acc[nt][0], A0.x, A1.x, A0.y, A1.y, bb.x, bb.y);
                mma_f16(acc[nt][1], A2.x, A3.x, A2.y, A3.y, bb.x, bb.y);
            }
        }

        // packed epilogue: bias + per-row ||p||^2 partials
        float2 S0 = make_float2(0.f, 0.f), S1 = S0, S2 = S0, S3 = S0;
        #pragma unroll
        for (int nt = 0; nt < 8; nt++) {
            int col = n0 + nt * 8 + 2 * tig;
            float2 b01 = *(const float2*)&b2s[col];
            float2 v0 = add2(make_float2(acc[nt][0][0], acc[nt][0][1]), b01);
            float2 v1 = add2(make_float2(acc[nt][0][2], acc[nt][0][3]), b01);
            float2 v2 = add2(make_float2(acc[nt][1][0], acc[nt][1][1]), b01);
            float2 v3 = add2(make_float2(acc[nt][1][2], acc[nt][1][3]), b01);
            S0 = fma2(v0, v0, S0);
            S1 = fma2(v1, v1, S1);
            S2 = fma2(v2, v2, S2);
            S3 = fma2(v3, v3, S3);
            acc[nt][0][0] = v0.x; acc[nt][0][1] = v0.y;
            acc[nt][0][2] = v1.x; acc[nt][0][3] = v1.y;
            acc[nt][1][0] = v2.x; acc[nt][1][1] = v2.y;
            acc[nt][1][2] = v3.x; acc[nt][1][3] = v3.y;
        }
        float s0 = S0.x + S0.y, s1 = S1.x + S1.y;
        float s2 = S2.x + S2.y, s3 = S3.x + S3.y;
        s0 += __shfl_xor_sync(0xffffffffu, s0, 1); s0 += __shfl_xor_sync(0xffffffffu, s0, 2);
        s1 += __shfl_xor_sync(0xffffffffu, s1, 1); s1 += __shfl_xor_sync(0xffffffffu, s1, 2);
        s2 += __shfl_xor_sync(0xffffffffu, s2, 1); s2 += __shfl_xor_sync(0xffffffffu, s2, 2);
        s3 += __shfl_xor_sync(0xffffffffu, s3, 1); s3 += __shfl_xor_sync(0xffffffffu, s3, 2);
        if (tig == 0) {
            r2p[ng * 128 + mr]      = s0;
            r2p[ng * 128 + mr + 8]  = s1;
            r2p[ng * 128 + mr + 16] = s2;
            r2p[ng * 128 + mr + 24] = s3;
        }
        __syncthreads();

        // Lambert-W Newton (reference recurrence; converged <10 iters at fp32)
        if (tid < 128) {
            float r2 = r2p[tid] + r2p[128 + tid] + r2p[256 + tid] + r2p[384 + tid];
            float w = log1pf(r2);
            #pragma unroll
            for (int it = 0; it < 10; it++) {
                float ew  = __expf(w);
                float num = fmaf(w, ew, -r2);
                float den = fmaf(w, ew, ew);
                w = w - __fdividef(num, den);
            }
            w = fmaxf(w, 0.0f);
            float tn = sqrtf(w);
            float rr = sqrtf(r2);
            float scale = (rr > 1e-12f) ? __fdividef(tn, fmaxf(rr, 1e-12f)) : 1.0f;
            scs[tid] = -scale;
        }
        __syncthreads();

        const float2 sc0 = make_float2(scs[mr], scs[mr]);
        const float2 sc1 = make_float2(scs[mr + 8], scs[mr + 8]);
        const float2 sc2 = make_float2(scs[mr + 16], scs[mr + 16]);
        const float2 sc3 = make_float2(scs[mr + 24], scs[mr + 24]);
        const size_t rb = ((size_t)tile * 128 + mr) * Dq;
        #pragma unroll
        for (int nt = 0; nt < 8; nt++) {
            int col = n0 + nt * 8 + 2 * tig;
            *(float2*)&out[rb + col]           = mul2(sc0, make_float2(acc[nt][0][0], acc[nt][0][1]));
            *(float2*)&out[rb + 8  * Dq + col] = mul2(sc1, make_float2(acc[nt][0][2], acc[nt][0][3]));
            *(float2*)&out[rb + 16 * Dq + col] = mul2(sc2, make_float2(acc[nt][1][0], acc[nt][1][1]));
            *(float2*)&out[rb + 24 * Dq + col] = mul2(sc3, make_float2(acc[nt][1][2], acc[nt][1][3]));
        }
        bi ^= 1;
    }
}

// ---------------- launch ----------------
extern "C" void kernel_launch(void* const* d_in, const int* in_sizes, int n_in,
                              void* d_out, int out_size)
{
    const float* z  = (const float*)d_in[0];
    const float* t  = (const float*)d_in[1];
    const float* W1 = (const float*)d_in[2];
    const float* b1 = (const float*)d_in[3];
    const float* W2 = (const float*)d_in[4];
    const float* b2 = (const float*)d_in[5];
    float* out = (float*)d_out;

    cudaFuncSetAttribute(k1_hidden, cudaFuncAttributeMaxDynamicSharedMemorySize, SMEM1);
    cudaFuncSetAttribute(k2_policy, cudaFuncAttributeMaxDynamicSharedMemorySize, SMEM2);

    k1_hidden<<<GRID, NT, SMEM1>>>(z, t, W1, b1);
    k2_policy<<<GRID, NT, SMEM2>>>(W2, b2, out);
}

// round 9
// speedup vs baseline: 1.4289x; 1.0221x over previous
#include <cuda_runtime.h>

// CVXPolicy_Integrator, round 9: FUSED persistent fp16-mma kernel.
// Per 128-row tile: GEMM1 ([z,t]@W1, tanh) -> h in SMEM -> GEMM2 (h@W2+b2)
// -> r2 -> LambertW -> ustar. No g_H round trip through DRAM.

#define Bq    131072
#define Dq    256
#define Hq    100
#define HP    112          // padded hidden (7 k16-steps)
#define HPU   56           // u32 (half2) per h row
#define GRID  148
#define NT    512
#define NTILES (Bq / 128)  // 1024

#define W1SW  136          // w1t row stride in u32 (136%32==8)
#define XSW   24           // xs row stride in u32  (24%32==24)
#define XBUF  (128 * XSW)
#define KP1U  136          // GEMM1 K in u32 (272 halves: 256 z + t + pad)

// ---------------- helpers ----------------
__device__ __forceinline__ unsigned pack_h2(float lo, float hi) {
    unsigned u;
    asm("cvt.rn.f16x2.f32 %0, %1, %2;" : "=r"(u) : "f"(hi), "f"(lo));
    return u;
}
__device__ __forceinline__ void mma_f16(float* c,
                                        unsigned a0, unsigned a1, unsigned a2, unsigned a3,
                                        unsigned b0, unsigned b1) {
    asm volatile(
        "mma.sync.aligned.m16n8k16.row.col.f32.f16.f16.f32 "
        "{%0,%1,%2,%3}, {%4,%5,%6,%7}, {%8,%9}, {%0,%1,%2,%3};"
        : "+f"(c[0]), "+f"(c[1]), "+f"(c[2]), "+f"(c[3])
        : "r"(a0), "r"(a1), "r"(a2), "r"(a3), "r"(b0), "r"(b1));
}
// u32-granularity perm within 8-blocks: pairs {u,u+4} -> {2v,2v+1}
__device__ __forceinline__ int permu(int u) {
    return (u & ~7) | ((u & 3) << 1) | ((u >> 2) & 1);
}

union F2U { float2 f; unsigned long long u; };
__device__ __forceinline__ float2 add2(float2 a, float2 b) {
    F2U A, B, C; A.f = a; B.f = b;
    asm("add.rn.f32x2 %0, %1, %2;" : "=l"(C.u) : "l"(A.u), "l"(B.u));
    return C.f;
}
__device__ __forceinline__ float2 fma2(float2 a, float2 b, float2 c) {
    F2U A, B, C, D; A.f = a; B.f = b; C.f = c;
    asm("fma.rn.f32x2 %0, %1, %2, %3;" : "=l"(D.u) : "l"(A.u), "l"(B.u), "l"(C.u));
    return D.f;
}
__device__ __forceinline__ float2 mul2(float2 a, float2 b) {
    F2U A, B, C; A.f = a; B.f = b;
    asm("mul.rn.f32x2 %0, %1, %2;" : "=l"(C.u) : "l"(A.u), "l"(B.u));
    return C.f;
}

__device__ __forceinline__ float tanh_fast(float x) {
    float ax = fabsf(x);
    float e  = __expf(-2.0f * ax);
    float y  = 1.0f + e;
    float r  = __uint_as_float(0x7EF311C3u - __float_as_uint(y));
    r = r * (2.0f - y * r);
    r = r * (2.0f - y * r);
    r = r * (2.0f - y * r);
    float th = fmaf(-2.0f * e, r, 1.0f);
    return copysignf(th, x);
}

// ---------------- smem layout (u32 words) ----------------
#define OFF_W1T  0
#define OFF_W2T  (OFF_W1T + HP * W1SW)          // 15232
#define OFF_XS   (OFF_W2T + Dq * HPU)           // +14336 = 29568
#define OFF_HS   (OFF_XS + 3 * XBUF)            // +9216  = 38784
#define OFF_F32  (OFF_HS + 128 * HPU)           // +7168  = 45952
// f32 region: b1s[112] b2s[256] r2p[512] scs[128]
#define SMEMT    ((OFF_F32 + HP + Dq + 512 + 128) * 4)   // ~187.9 KB

__global__ void __launch_bounds__(NT, 1)
fused_policy(const float* __restrict__ z, const float* __restrict__ t,
             const float* __restrict__ W1, const float* __restrict__ b1,
             const float* __restrict__ W2, const float* __restrict__ b2,
             float* __restrict__ out)
{
    extern __shared__ unsigned sm[];
    unsigned* w1t = sm + OFF_W1T;
    unsigned* w2t = sm + OFF_W2T;
    unsigned* xs  = sm + OFF_XS;
    unsigned* hs  = sm + OFF_HS;
    float*    b1s = (float*)(sm + OFF_F32);
    float*    b2s = b1s + HP;
    float*    r2p = b2s + Dq;      // [4][128]
    float*    scs = r2p + 512;     // [128]

    const int tid = threadIdx.x;

    // ---- one-time weight loads ----
    // W1 -> w1t[n][perm(u)] half2. X col kk<256 pairs W1 row kk+1; kk=256 -> row 0.
    for (int idx = tid; idx < HP * KP1U; idx += NT) {
        int u = idx / HP, n = idx - u * HP;
        float f0 = 0.0f, f1 = 0.0f;
        if (n < Hq) {
            int k0 = 2 * u, k1 = 2 * u + 1;
            f0 = (k0 == 256) ? W1[n] : ((k0 < 256) ? W1[(k0 + 1) * Hq + n] : 0.0f);
            f1 = (k1 == 256) ? W1[n] : ((k1 < 256) ? W1[(k1 + 1) * Hq + n] : 0.0f);
        }
        w1t[n * W1SW + permu(u)] = pack_h2(f0, f1);
    }
    // W2 -> w2t[n][perm(u)] half2 (k pads 100..111 zero)
    for (int idx = tid; idx < HPU * Dq; idx += NT) {
        int u = idx >> 8, n = idx & 255;
        int k0 = 2 * u, k1 = 2 * u + 1;
        float f0 = (k0 < Hq) ? W2[k0 * Dq + n] : 0.0f;
        float f1 = (k1 < Hq) ? W2[k1 * Dq + n] : 0.0f;
        w2t[n * HPU + permu(u)] = pack_h2(f0, f1);
    }
    if (tid < HP) b1s[tid] = (tid < Hq) ? b1[tid] : 0.0f;
    if (tid < Dq) b2s[tid] = b2[tid];

    const int warp = tid >> 5, lane = tid & 31;
    const int gid = lane >> 2, tig = lane & 3;
    const int m0  = (warp & 3) * 32;
    const int ng  = warp >> 2;                               // 4 n-groups
    const int tb  = (ng < 2) ? 4 * ng : (8 + 3 * (ng - 2));  // GEMM1 tiles {0,4,8,11}
    const int ntc = (ng < 2) ? 4 : 3;                        // counts {4,4,3,3}
    const int n0  = ng * 64;                                 // GEMM2 n-base
    const int mr  = m0 + gid;

    // ---- z staging: thread = (row sr, quarter sb) of each 32-col chunk ----
    const int sr = tid >> 2, sb = tid & 3;
    const int q0 = (sb >> 1) * 4 + (sb & 1);   // float4 indices {0,1,4,5}; +2 pairs

    int pt = blockIdx.x, pc = 0;
    float4 rA = make_float4(0.f, 0.f, 0.f, 0.f), rB = rA;

    #define K1_LDG() do {                                                        \
        if (pt < NTILES) {                                                       \
            if (pc < 8) {                                                        \
                const float4* src = (const float4*)z                             \
                    + ((size_t)(pt * 128 + sr)) * 64 + pc * 8;                   \
                rA = src[q0]; rB = src[q0 + 2];                                  \
            } else {                                                             \
                rA = make_float4(0.f, 0.f, 0.f, 0.f); rB = rA;                   \
                if (sb == 0) rA.x = t[pt * 128 + sr];                            \
            }                                                                    \
        }                                                                        \
        pc++; if (pc == 9) { pc = 0; pt += GRID; }                               \
    } while (0)

    #define K1_STS(bs) do {                                                      \
        unsigned* d = xs + (bs) * XBUF + sr * XSW + sb * 4;                      \
        uint4 u;                                                                 \
        u.x = pack_h2(rA.x, rA.y); u.y = pack_h2(rB.x, rB.y);                    \
        u.z = pack_h2(rA.z, rA.w); u.w = pack_h2(rB.z, rB.w);                    \
        *(uint4*)d = u;                                                          \
    } while (0)

    K1_LDG();
    K1_STS(0);
    K1_LDG();
    __syncthreads();

    float acc[4][2][4];
    #pragma unroll
    for (int nt = 0; nt < 4; nt++)
        #pragma unroll
        for (int mf = 0; mf < 2; mf++)
            #pragma unroll
            for (int i = 0; i < 4; i++) acc[nt][mf][i] = 0.0f;

    int bcur = 0;
    for (int tile = blockIdx.x; tile < NTILES; tile += GRID) {
        // ======== GEMM1: h = tanh([z,t]@W1+b1) ========
        for (int cc = 0; cc < 9; cc++) {
            int bnext = bcur + 1; if (bnext == 3) bnext = 0;
            K1_STS(bnext);
            K1_LDG();
            __syncthreads();

            const unsigned* xa = xs + bcur * XBUF + mr * XSW + 2 * tig;
            const unsigned* wb = w1t + (tb * 8 + gid) * W1SW + cc * 16 + 2 * tig;
            const int kst = (cc == 8) ? 1 : 2;
            #pragma unroll
            for (int ks = 0; ks < 2; ks++) {
                if (ks < kst) {
                    const int u0 = ks * 8;
                    uint2 A0 = *(const uint2*)(xa + u0);
                    uint2 A1 = *(const uint2*)(xa + 8 * XSW + u0);
                    uint2 A2 = *(const uint2*)(xa + 16 * XSW + u0);
                    uint2 A3 = *(const uint2*)(xa + 24 * XSW + u0);
                    #pragma unroll
                    for (int nt = 0; nt < 4; nt++) {
                        if (nt < ntc) {
                            uint2 bb = *(const uint2*)(wb + nt * 8 * W1SW + u0);
                            mma_f16(acc[nt][0], A0.x, A1.x, A0.y, A1.y, bb.x, bb.y);
                            mma_f16(acc[nt][1], A2.x, A3.x, A2.y, A3.y, bb.x, bb.y);
                        }
                    }
                }
            }
            bcur = bnext;
        }

        // ======== epilogue1: bias + tanh -> hs (SMEM, k-permuted half2) ========
        #pragma unroll
        for (int nt = 0; nt < 4; nt++) {
            if (nt < ntc) {
                int u   = (tb + nt) * 4 + tig;     // u32 index: halves {2u,2u+1}
                int col = 2 * u;
                int pos = permu(u);
                float bb0 = b1s[col], bb1 = b1s[col + 1];
                #pragma unroll
                for (int mf = 0; mf < 2; mf++) {
                    int r0 = mr + mf * 16;
                    hs[r0 * HPU + pos] =
                        pack_h2(tanh_fast(acc[nt][mf][0] + bb0), tanh_fast(acc[nt][mf][1] + bb1));
                    hs[(r0 + 8) * HPU + pos] =
                        pack_h2(tanh_fast(acc[nt][mf][2] + bb0), tanh_fast(acc[nt][mf][3] + bb1));
                    acc[nt][mf][0] = acc[nt][mf][1] = acc[nt][mf][2] = acc[nt][mf][3] = 0.0f;
                }
            }
        }
        __syncthreads();   // hs complete

        // ======== GEMM2: p = h@W2+b2; r2; scale; store ========
        float a2c[8][2][4];
        #pragma unroll
        for (int nt = 0; nt < 8; nt++)
            #pragma unroll
            for (int mf = 0; mf < 2; mf++)
                #pragma unroll
                for (int i = 0; i < 4; i++) a2c[nt][mf][i] = 0.0f;

        const unsigned* ha = hs + mr * HPU + 2 * tig;
        const unsigned* wb2 = w2t + (n0 + gid) * HPU + 2 * tig;

        #pragma unroll
        for (int ks = 0; ks < 7; ks++) {
            const int u0 = ks * 8;
            uint2 A0 = *(const uint2*)(ha + u0);
            uint2 A1 = *(const uint2*)(ha + 8 * HPU + u0);
            uint2 A2 = *(const uint2*)(ha + 16 * HPU + u0);
            uint2 A3 = *(const uint2*)(ha + 24 * HPU + u0);
            #pragma unroll
            for (int nt = 0; nt < 8; nt++) {
                uint2 bb = *(const uint2*)(wb2 + nt * 8 * HPU + u0);
                mma_f16(a2c[nt][0], A0.x, A1.x, A0.y, A1.y, bb.x, bb.y);
                mma_f16(a2c[nt][1], A2.x, A3.x, A2.y, A3.y, bb.x, bb.y);
            }
        }

        float2 S0 = make_float2(0.f, 0.f), S1 = S0, S2 = S0, S3 = S0;
        #pragma unroll
        for (int nt = 0; nt < 8; nt++) {
            int col = n0 + nt * 8 + 2 * tig;
            float2 b01 = *(const float2*)&b2s[col];
            float2 v0 = add2(make_float2(a2c[nt][0][0], a2c[nt][0][1]), b01);
            float2 v1 = add2(make_float2(a2c[nt][0][2], a2c[nt][0][3]), b01);
            float2 v2 = add2(make_float2(a2c[nt][1][0], a2c[nt][1][1]), b01);
            float2 v3 = add2(make_float2(a2c[nt][1][2], a2c[nt][1][3]), b01);
            S0 = fma2(v0, v0, S0);
            S1 = fma2(v1, v1, S1);
            S2 = fma2(v2, v2, S2);
            S3 = fma2(v3, v3, S3);
            a2c[nt][0][0] = v0.x; a2c[nt][0][1] = v0.y;
            a2c[nt][0][2] = v1.x; a2c[nt][0][3] = v1.y;
            a2c[nt][1][0] = v2.x; a2c[nt][1][1] = v2.y;
            a2c[nt][1][2] = v3.x; a2c[nt][1][3] = v3.y;
        }
        float s0 = S0.x + S0.y, s1 = S1.x + S1.y;
        float s2 = S2.x + S2.y, s3 = S3.x + S3.y;
        s0 += __shfl_xor_sync(0xffffffffu, s0, 1); s0 += __shfl_xor_sync(0xffffffffu, s0, 2);
        s1 += __shfl_xor_sync(0xffffffffu, s1, 1); s1 += __shfl_xor_sync(0xffffffffu, s1, 2);
        s2 += __shfl_xor_sync(0xffffffffu, s2, 1); s2 += __shfl_xor_sync(0xffffffffu, s2, 2);
        s3 += __shfl_xor_sync(0xffffffffu, s3, 1); s3 += __shfl_xor_sync(0xffffffffu, s3, 2);
        if (tig == 0) {
            r2p[ng * 128 + mr]      = s0;
            r2p[ng * 128 + mr + 8]  = s1;
            r2p[ng * 128 + mr + 16] = s2;
            r2p[ng * 128 + mr + 24] = s3;
        }
        __syncthreads();

        // Lambert-W Newton (reference recurrence)
        if (tid < 128) {
            float r2 = r2p[tid] + r2p[128 + tid] + r2p[256 + tid] + r2p[384 + tid];
            float w = log1pf(r2);
            #pragma unroll
            for (int it = 0; it < 10; it++) {
                float ew  = __expf(w);
                float num = fmaf(w, ew, -r2);
                float den = fmaf(w, ew, ew);
                w = w - __fdividef(num, den);
            }
            w = fmaxf(w, 0.0f);
            float tn = sqrtf(w);
            float rr = sqrtf(r2);
            float scale = (rr > 1e-12f) ? __fdividef(tn, fmaxf(rr, 1e-12f)) : 1.0f;
            scs[tid] = -scale;
        }
        __syncthreads();

        const float2 sc0 = make_float2(scs[mr], scs[mr]);
        const float2 sc1 = make_float2(scs[mr + 8], scs[mr + 8]);
        const float2 sc2 = make_float2(scs[mr + 16], scs[mr + 16]);
        const float2 sc3 = make_float2(scs[mr + 24], scs[mr + 24]);
        const size_t rb = ((size_t)tile * 128 + mr) * Dq;
        #pragma unroll
        for (int nt = 0; nt < 8; nt++) {
            int col = n0 + nt * 8 + 2 * tig;
            *(float2*)&out[rb + col]           = mul2(sc0, make_float2(a2c[nt][0][0], a2c[nt][0][1]));
            *(float2*)&out[rb + 8  * Dq + col] = mul2(sc1, make_float2(a2c[nt][0][2], a2c[nt][0][3]));
            *(float2*)&out[rb + 16 * Dq + col] = mul2(sc2, make_float2(a2c[nt][1][0], a2c[nt][1][1]));
            *(float2*)&out[rb + 24 * Dq + col] = mul2(sc3, make_float2(a2c[nt][1][2], a2c[nt][1][3]));
        }
    }
}

// ---------------- launch ----------------
extern "C" void kernel_launch(void* const* d_in, const int* in_sizes, int n_in,
                              void* d_out, int out_size)
{
    const float* z  = (const float*)d_in[0];
    const float* t  = (const float*)d_in[1];
    const float* W1 = (const float*)d_in[2];
    const float* b1 = (const float*)d_in[3];
    const float* W2 = (const float*)d_in[4];
    const float* b2 = (const float*)d_in[5];
    float* out = (float*)d_out;

    cudaFuncSetAttribute(fused_policy, cudaFuncAttributeMaxDynamicSharedMemorySize, SMEMT);
    fused_policy<<<GRID, NT, SMEMT>>>(z, t, W1, b1, W2, b2, out);
}

// round 11
// speedup vs baseline: 1.6265x; 1.1383x over previous
#include <cuda_runtime.h>
#include <cstdint>

// CVXPolicy_Integrator, round 11: fused persistent fp16-HMMA kernel with
// cp.async-pipelined z staging (3-deep f32 ring + smem convert pass) and the
// t-column folded into epilogue1 as a rank-1 f32 term (GEMM1 K=256, 16 ksteps).

#define Bq 131072
#define Dq 256
#define Hq 100
#define GRID 148
#define NT 512
#define NTILES (Bq / 128)

#define W1SW 136           // w1t row stride u32 (136%32==8)
#define XSW  24            // xs row stride u32 (24%32==24)
#define XBUF (128 * XSW)   // 3072 u32 per fp16 chunk buffer
#define HPU  56            // h row width in u32 (112 halves)

// ---- smem u32 offsets ----
#define OFF_W1  0                          // 104*136 = 14144
#define OFF_W2  (OFF_W1 + 104 * W1SW)      // 256*56 = 14336
#define OFF_ZF  (OFF_W2 + 256 * HPU)       // 3*4096 f32-chunk ring
#define OFF_XS  (OFF_ZF + 3 * 4096)        // 2*3072 fp16 chunk ring
#define OFF_HS  (OFF_XS + 2 * XBUF)        // 128*56
#define OFF_F32 (OFF_HS + 128 * HPU)
// f32 region: w1r0[104] b1s[104] b2s[256] tss[128] r2p[512] scs[128]
#define SMEMT ((OFF_F32 + 104 + 104 + 256 + 128 + 512 + 128) * 4)   // ~216 KB

// ---------------- helpers ----------------
__device__ __forceinline__ unsigned pack_h2(float lo, float hi) {
    unsigned u;
    asm("cvt.rn.f16x2.f32 %0, %1, %2;" : "=r"(u) : "f"(hi), "f"(lo));
    return u;
}
__device__ __forceinline__ void mma_f16(float* c,
                                        unsigned a0, unsigned a1, unsigned a2, unsigned a3,
                                        unsigned b0, unsigned b1) {
    asm volatile(
        "mma.sync.aligned.m16n8k16.row.col.f32.f16.f16.f32 "
        "{%0,%1,%2,%3}, {%4,%5,%6,%7}, {%8,%9}, {%0,%1,%2,%3};"
        : "+f"(c[0]), "+f"(c[1]), "+f"(c[2]), "+f"(c[3])
        : "r"(a0), "r"(a1), "r"(a2), "r"(a3), "r"(b0), "r"(b1));
}
__device__ __forceinline__ void cp_async16(void* sdst, const void* gsrc) {
    unsigned s = (unsigned)__cvta_generic_to_shared(sdst);
    asm volatile("cp.async.cg.shared.global [%0], [%1], 16;" :: "r"(s), "l"(gsrc));
}
#define CP_COMMIT() asm volatile("cp.async.commit_group;")
#define CP_WAIT(n)  asm volatile("cp.async.wait_group %0;" :: "n"(n))

// within 8-u32 blocks: pairs {u, u+4} -> adjacent positions {2v, 2v+1}
__device__ __forceinline__ int permu(int u) {
    return (u & ~7) | ((u & 3) << 1) | ((u >> 2) & 1);
}

union F2U { float2 f; unsigned long long u; };
__device__ __forceinline__ float2 add2(float2 a, float2 b) {
    F2U A, B, C; A.f = a; B.f = b;
    asm("add.rn.f32x2 %0, %1, %2;" : "=l"(C.u) : "l"(A.u), "l"(B.u));
    return C.f;
}
__device__ __forceinline__ float2 fma2(float2 a, float2 b, float2 c) {
    F2U A, B, C, D; A.f = a; B.f = b; C.f = c;
    asm("fma.rn.f32x2 %0, %1, %2, %3;" : "=l"(D.u) : "l"(A.u), "l"(B.u), "l"(C.u));
    return D.f;
}
__device__ __forceinline__ float2 mul2(float2 a, float2 b) {
    F2U A, B, C; A.f = a; B.f = b;
    asm("mul.rn.f32x2 %0, %1, %2;" : "=l"(C.u) : "l"(A.u), "l"(B.u));
    return C.f;
}

__device__ __forceinline__ float tanh_fast(float x) {
    float ax = fabsf(x);
    float e  = __expf(-2.0f * ax);
    float y  = 1.0f + e;
    float r  = __uint_as_float(0x7EF311C3u - __float_as_uint(y));
    r = r * (2.0f - y * r);
    r = r * (2.0f - y * r);
    r = r * (2.0f - y * r);
    float th = fmaf(-2.0f * e, r, 1.0f);
    return copysignf(th, x);
}

__global__ void __launch_bounds__(NT, 1)
fused_policy(const float* __restrict__ z, const float* __restrict__ t,
             const float* __restrict__ W1, const float* __restrict__ b1,
             const float* __restrict__ W2, const float* __restrict__ b2,
             float* __restrict__ out)
{
    extern __shared__ unsigned sm[];
    unsigned* w1t = sm + OFF_W1;
    unsigned* w2t = sm + OFF_W2;
    unsigned* zf  = sm + OFF_ZF;
    unsigned* xs  = sm + OFF_XS;
    unsigned* hs  = sm + OFF_HS;
    float* w1r0 = (float*)(sm + OFF_F32);
    float* b1s  = w1r0 + 104;
    float* b2s  = b1s + 104;
    float* tss  = b2s + 256;
    float* r2p  = tss + 128;     // [4][128]
    float* scs  = r2p + 512;     // [128]

    const int tid = threadIdx.x;

    // ---- one-time weights ----
    // W1 -> w1t[n][permu(u)]: halves {2u,2u+1} = z-cols -> W1 rows {2u+1, 2u+2}.
    for (int idx = tid; idx < 128 * 104; idx += NT) {
        int u = idx / 104, n = idx - u * 104;
        float f0 = 0.f, f1 = 0.f;
        if (n < Hq) {
            f0 = W1[(2 * u + 1) * Hq + n];
            f1 = W1[(2 * u + 2) * Hq + n];
        }
        w1t[n * W1SW + permu(u)] = pack_h2(f0, f1);
    }
    // W2 -> w2t[n][permu(u)] (k >= 100 zero)
    for (int idx = tid; idx < HPU * Dq; idx += NT) {
        int u = idx >> 8, n = idx & 255;
        int k0 = 2 * u;
        float f0 = (k0 < Hq) ? W2[k0 * Dq + n] : 0.f;
        float f1 = (k0 + 1 < Hq) ? W2[(k0 + 1) * Dq + n] : 0.f;
        w2t[n * HPU + permu(u)] = pack_h2(f0, f1);
    }
    if (tid < 104) {
        w1r0[tid] = (tid < Hq) ? W1[tid] : 0.f;   // W1 row 0 (the t row)
        b1s[tid]  = (tid < Hq) ? b1[tid] : 0.f;
    }
    if (tid < Dq) b2s[tid] = b2[tid];
    // zero hs once (epi1 writes u<52 each tile; u52..55 must stay finite-zero)
    for (int idx = tid; idx < 128 * HPU; idx += NT) hs[idx] = 0u;

    const int warp = tid >> 5, lane = tid & 31;
    const int gid = lane >> 2, tig = lane & 3;
    const int m0  = (warp & 3) * 32;
    const int ng  = warp >> 2;                          // 4 n-groups over 13 tiles
    const int tb  = ng ? (1 + 3 * ng) : 0;              // {0,4,7,10}
    const int ntc = ng ? 3 : 4;                         // {4,3,3,3}
    const int n0  = ng * 64;                            // GEMM2 n-base
    const int mr  = m0 + gid;

    // ---- cp.async z pipeline: 8 chunks of 32 f32-cols per tile, ring of 3 ----
    int pt = blockIdx.x, pc = 0, pb = 0, cb = 0;

    #define ZISSUE() do {                                                        \
        if (pt < NTILES) {                                                       \
            const float4* srcb = (const float4*)z + ((size_t)pt * 128) * 64 + pc * 8; \
            float4* dst = (float4*)(zf + pb * 4096);                             \
            int r0_ = tid >> 3, c4_ = tid & 7;                                   \
            cp_async16(dst + tid,       srcb + (size_t)r0_ * 64 + c4_);          \
            cp_async16(dst + tid + 512, srcb + (size_t)(r0_ + 64) * 64 + c4_);   \
        }                                                                        \
        CP_COMMIT();                                                             \
        pc++; if (pc == 8) { pc = 0; pt += GRID; }                               \
        pb++; if (pb == 3) pb = 0;                                               \
    } while (0)

    // convert f32 chunk (zf[cb]) -> fp16 permuted xs[s&1]
    #define ZCONV(s) do {                                                        \
        const float4* s4 = (const float4*)(zf + cb * 4096);                      \
        unsigned* dx = xs + ((s) & 1) * XBUF;                                    \
        _Pragma("unroll")                                                        \
        for (int j = 0; j < 2; j++) {                                            \
            int q = tid + j * 512;                                               \
            int r = q >> 3, c4 = q & 7;                                          \
            float4 v = s4[q];                                                    \
            int pos0 = ((c4 & 1) << 2) | ((c4 >> 1) & 1) | ((c4 & 4) << 1);      \
            unsigned* dd = dx + r * XSW;                                         \
            dd[pos0]     = pack_h2(v.x, v.y);                                    \
            dd[pos0 + 2] = pack_h2(v.z, v.w);                                    \
        }                                                                        \
        cb++; if (cb == 3) cb = 0;                                               \
    } while (0)

    float acc[4][2][4];
    #pragma unroll
    for (int nt = 0; nt < 4; nt++)
        #pragma unroll
        for (int mf = 0; mf < 2; mf++)
            #pragma unroll
            for (int i = 0; i < 4; i++) acc[nt][mf][i] = 0.0f;

    // mma for GEMM1 chunk sc (k-offset sc*16 u32) from xs buffer bf
    #define MMA1(sc, bf) do {                                                    \
        const unsigned* xa = xs + (bf) * XBUF + mr * XSW + 2 * tig;              \
        const unsigned* wb = w1t + (tb * 8 + gid) * W1SW + (sc) * 16 + 2 * tig;  \
        _Pragma("unroll")                                                        \
        for (int ks = 0; ks < 2; ks++) {                                         \
            const int u0 = ks * 8;                                               \
            uint2 A0 = *(const uint2*)(xa + u0);                                 \
            uint2 A1 = *(const uint2*)(xa + 8 * XSW + u0);                       \
            uint2 A2 = *(const uint2*)(xa + 16 * XSW + u0);                      \
            uint2 A3 = *(const uint2*)(xa + 24 * XSW + u0);                      \
            _Pragma("unroll")                                                    \
            for (int nt = 0; nt < 4; nt++) {                                     \
                if (nt < ntc) {                                                  \
                    uint2 bb = *(const uint2*)(wb + nt * 8 * W1SW + u0);         \
                    mma_f16(acc[nt][0], A0.x, A1.x, A0.y, A1.y, bb.x, bb.y);     \
                    mma_f16(acc[nt][1], A2.x, A3.x, A2.y, A3.y, bb.x, bb.y);     \
                }                                                                \
            }                                                                    \
        }                                                                        \
    } while (0)

    ZISSUE();          // group 0
    ZISSUE();          // group 1
    __syncthreads();   // weights + hs zeros visible

    for (int tile = blockIdx.x; tile < NTILES; tile += GRID) {
        if (tid < 128) tss[tid] = t[tile * 128 + tid];

        // ---- GEMM1: 8 pipelined chunk steps ----
        for (int s = 0; s < 8; s++) {
            CP_WAIT(1);          // group for chunk s landed (own thread)
            ZISSUE();            // issue chunk s+2 (buffer safe: converted at s-1)
            __syncthreads();     // chunk s visible to all; xs[s&1] free
            ZCONV(s);
            if (s > 0) MMA1(s - 1, (s - 1) & 1);
        }
        __syncthreads();
        MMA1(7, 1);

        // ---- epilogue1: bias + t*W1row0 + tanh -> hs (fp16, permuted) ----
        {
            const float tA0 = tss[mr],      tB0 = tss[mr + 8];
            const float tA1 = tss[mr + 16], tB1 = tss[mr + 24];
            #pragma unroll
            for (int nt = 0; nt < 4; nt++) {
                if (nt < ntc) {
                    int u = (tb + nt) * 4 + tig;
                    int col = 2 * u;
                    int pos = permu(u);
                    float bb0 = b1s[col], bb1 = b1s[col + 1];
                    float w0 = w1r0[col], w1v = w1r0[col + 1];
                    hs[mr * HPU + pos] = pack_h2(
                        tanh_fast(fmaf(tA0, w0, acc[nt][0][0] + bb0)),
                        tanh_fast(fmaf(tA0, w1v, acc[nt][0][1] + bb1)));
                    hs[(mr + 8) * HPU + pos] = pack_h2(
                        tanh_fast(fmaf(tB0, w0, acc[nt][0][2] + bb0)),
                        tanh_fast(fmaf(tB0, w1v, acc[nt][0][3] + bb1)));
                    hs[(mr + 16) * HPU + pos] = pack_h2(
                        tanh_fast(fmaf(tA1, w0, acc[nt][1][0] + bb0)),
                        tanh_fast(fmaf(tA1, w1v, acc[nt][1][1] + bb1)));
                    hs[(mr + 24) * HPU + pos] = pack_h2(
                        tanh_fast(fmaf(tB1, w0, acc[nt][1][2] + bb0)),
                        tanh_fast(fmaf(tB1, w1v, acc[nt][1][3] + bb1)));
                    #pragma unroll
                    for (int mf = 0; mf < 2; mf++)
                        acc[nt][mf][0] = acc[nt][mf][1] = acc[nt][mf][2] = acc[nt][mf][3] = 0.0f;
                }
            }
        }
        __syncthreads();   // hs complete

        // ---- GEMM2: p = h@W2+b2 ----
        float a2c[8][2][4];
        #pragma unroll
        for (int nt = 0; nt < 8; nt++)
            #pragma unroll
            for (int mf = 0; mf < 2; mf++)
                #pragma unroll
                for (int i = 0; i < 4; i++) a2c[nt][mf][i] = 0.0f;

        const unsigned* ha = hs + mr * HPU + 2 * tig;
        const unsigned* wb2 = w2t + (n0 + gid) * HPU + 2 * tig;

        #pragma unroll
        for (int ks = 0; ks < 7; ks++) {
            const int u0 = ks * 8;
            uint2 A0 = *(const uint2*)(ha + u0);
            uint2 A1 = *(const uint2*)(ha + 8 * HPU + u0);
            uint2 A2 = *(const uint2*)(ha + 16 * HPU + u0);
            uint2 A3 = *(const uint2*)(ha + 24 * HPU + u0);
            #pragma unroll
            for (int nt = 0; nt < 8; nt++) {
                uint2 bb = *(const uint2*)(wb2 + nt * 8 * HPU + u0);
                mma_f16(a2c[nt][0], A0.x, A1.x, A0.y, A1.y, bb.x, bb.y);
                mma_f16(a2c[nt][1], A2.x, A3.x, A2.y, A3.y, bb.x, bb.y);
            }
        }

        // ---- epilogue2: bias + r2 + Lambert + scale + store ----
        float2 S0 = make_float2(0.f, 0.f), S1 = S0, S2 = S0, S3 = S0;
        #pragma unroll
        for (int nt = 0; nt < 8; nt++) {
            int col = n0 + nt * 8 + 2 * tig;
            float2 b01 = *(const float2*)&b2s[col];
            float2 v0 = add2(make_float2(a2c[nt][0][0], a2c[nt][0][1]), b01);
            float2 v1 = add2(make_float2(a2c[nt][0][2], a2c[nt][0][3]), b01);
            float2 v2 = add2(make_float2(a2c[nt][1][0], a2c[nt][1][1]), b01);
            float2 v3 = add2(make_float2(a2c[nt][1][2], a2c[nt][1][3]), b01);
            S0 = fma2(v0, v0, S0);
            S1 = fma2(v1, v1, S1);
            S2 = fma2(v2, v2, S2);
            S3 = fma2(v3, v3, S3);
            a2c[nt][0][0] = v0.x; a2c[nt][0][1] = v0.y;
            a2c[nt][0][2] = v1.x; a2c[nt][0][3] = v1.y;
            a2c[nt][1][0] = v2.x; a2c[nt][1][1] = v2.y;
            a2c[nt][1][2] = v3.x; a2c[nt][1][3] = v3.y;
        }
        float s0 = S0.x + S0.y, s1 = S1.x + S1.y;
        float s2 = S2.x + S2.y, s3 = S3.x + S3.y;
        s0 += __shfl_xor_sync(0xffffffffu, s0, 1); s0 += __shfl_xor_sync(0xffffffffu, s0, 2);
        s1 += __shfl_xor_sync(0xffffffffu, s1, 1); s1 += __shfl_xor_sync(0xffffffffu, s1, 2);
        s2 += __shfl_xor_sync(0xffffffffu, s2, 1); s2 += __shfl_xor_sync(0xffffffffu, s2, 2);
        s3 += __shfl_xor_sync(0xffffffffu, s3, 1); s3 += __shfl_xor_sync(0xffffffffu, s3, 2);
        if (tig == 0) {
            r2p[ng * 128 + mr]      = s0;
            r2p[ng * 128 + mr + 8]  = s1;
            r2p[ng * 128 + mr + 16] = s2;
            r2p[ng * 128 + mr + 24] = s3;
        }
        __syncthreads();

        if (tid < 128) {
            float rr2 = r2p[tid] + r2p[128 + tid] + r2p[256 + tid] + r2p[384 + tid];
            float w = log1pf(rr2);
            #pragma unroll
            for (int it = 0; it < 10; it++) {
                float ew  = __expf(w);
                float num = fmaf(w, ew, -rr2);
                float den = fmaf(w, ew, ew);
                w = w - __fdividef(num, den);
            }
            w = fmaxf(w, 0.0f);
            float tn = sqrtf(w);
            float rr = sqrtf(rr2);
            float scale = (rr > 1e-12f) ? __fdividef(tn, fmaxf(rr, 1e-12f)) : 1.0f;
            scs[tid] = -scale;
        }
        __syncthreads();

        const float2 sc0 = make_float2(scs[mr], scs[mr]);
        const float2 sc1 = make_float2(scs[mr + 8], scs[mr + 8]);
        const float2 sc2 = make_float2(scs[mr + 16], scs[mr + 16]);
        const float2 sc3 = make_float2(scs[mr + 24], scs[mr + 24]);
        const size_t rb = ((size_t)tile * 128 + mr) * Dq;
        #pragma unroll
        for (int nt = 0; nt < 8; nt++) {
            int col = n0 + nt * 8 + 2 * tig;
            *(float2*)&out[rb + col]           = mul2(sc0, make_float2(a2c[nt][0][0], a2c[nt][0][1]));
            *(float2*)&out[rb + 8  * Dq + col] = mul2(sc1, make_float2(a2c[nt][0][2], a2c[nt][0][3]));
            *(float2*)&out[rb + 16 * Dq + col] = mul2(sc2, make_float2(a2c[nt][1][0], a2c[nt][1][1]));
            *(float2*)&out[rb + 24 * Dq + col] = mul2(sc3, make_float2(a2c[nt][1][2], a2c[nt][1][3]));
        }
    }
}

// ---------------- launch ----------------
extern "C" void kernel_launch(void* const* d_in, const int* in_sizes, int n_in,
                              void* d_out, int out_size)
{
    const float* z  = (const float*)d_in[0];
    const float* t  = (const float*)d_in[1];
    const float* W1 = (const float*)d_in[2];
    const float* b1 = (const float*)d_in[3];
    const float* W2 = (const float*)d_in[4];
    const float* b2 = (const float*)d_in[5];
    float* out = (float*)d_out;

    cudaFuncSetAttribute(fused_policy, cudaFuncAttributeMaxDynamicSharedMemorySize, SMEMT);
    fused_policy<<<GRID, NT, SMEMT>>>(z, t, W1, b1, W2, b2, out);
}